// round 14
// baseline (speedup 1.0000x reference)
#include <cuda_runtime.h>
#include <cstdint>

#define BATCH 16384
#define STEPS 32
#define LAT   64
#define IN_W  (STEPS * (2 * LAT + 1) + 2 * LAT)   // 4256 floats per row
#define WARPS_PER_BLOCK 8
#define NTHREADS 256
#define ROWS_PER_WARP 2
#define ROWS_PER_BLOCK (WARPS_PER_BLOCK * ROWS_PER_WARP)   // 16
#define NBLOCKS (BATCH / ROWS_PER_BLOCK)                   // 1024
#define BOFF ((2 + 2 * STEPS) * LAT)              // 4224: bias offset in row

#define SUPER 4                                    // steps per super-stage (1KB burst/stream)
#define NSUPER (STEPS / SUPER)                     // 8
#define STEP_BYTES 1024                            // per warp per step: 2 rows * (256 u + 256 w)
#define STAGE_BYTES (SUPER * STEP_BYTES)           // 4096
#define WARP_PIPE_BYTES (2 * STAGE_BYTES)          // 8192 (double buffer)
#define SMEM_BYTES (WARPS_PER_BLOCK * WARP_PIPE_BYTES)   // 65536

// scratch for deterministic single-kernel loss reduction (no allocations allowed)
__device__ float g_partials[NBLOCKS];
__device__ unsigned int g_count = 0;   // ticket counter; last block resets to 0

__device__ __forceinline__ void cp16(uint32_t dst_smem, const void* src) {
    asm volatile("cp.async.cg.shared.global [%0], [%1], 16;\n"
                 :: "r"(dst_smem), "l"(src) : "memory");
}
#define CP_COMMIT() asm volatile("cp.async.commit_group;\n" ::: "memory")
#define CP_WAIT1()  asm volatile("cp.async.wait_group 1;\n" ::: "memory")

__global__ void __launch_bounds__(NTHREADS, 3)
planar_flow_kernel(const float* __restrict__ in,
                   const float* __restrict__ noise,
                   float* __restrict__ out, int out_size)
{
    extern __shared__ __align__(16) unsigned char pipe[];   // SMEM_BYTES
    __shared__ float sacc[WARPS_PER_BLOCK];
    __shared__ bool  is_last;

    const int warp = threadIdx.x >> 5;
    const int lane = threadIdx.x & 31;
    const int h    = lane & 15;                    // position within my row's 16-lane group
    const int row  = blockIdx.x * ROWS_PER_BLOCK + warp * ROWS_PER_WARP + (lane >> 4);

    const float* rp = in + (size_t)row * IN_W;     // 17024 B/row: 16B aligned

    // per-lane global byte pointers into this row's u / w regions (16B chunk per step)
    const char* Ug = (const char*)(rp + 2 * LAT)           + h * 16;
    const char* Wg = (const char*)(rp + (2 + STEPS) * LAT) + h * 16;

    const uint32_t wbase = (uint32_t)__cvta_generic_to_shared(pipe) + warp * WARP_PIPE_BYTES;
    const uint32_t lch   = (lane >> 4) * 256 + h * 16;   // lane's slot within a 512B u/w block

    // ---- prologue: prime both super-stages; each stream gets a 1KB contiguous burst ----
    #pragma unroll
    for (int k = 0; k < 2; k++) {
        uint32_t sb = wbase + k * STAGE_BYTES;
        #pragma unroll
        for (int j = 0; j < SUPER; j++) {
            cp16(sb + j * STEP_BYTES + lch,       Ug + (k * SUPER + j) * 256);
            cp16(sb + j * STEP_BYTES + 512 + lch, Wg + (k * SUPER + j) * 256);
        }
        CP_COMMIT();
    }

    // --- z0 = mu + noise * exp(0.5*logsigma2), 4 elements per lane ---
    const float4* rp4 = (const float4*)rp;
    float4 mu = rp4[h];                                            // floats [0,64)
    float4 ls = rp4[16 + h];                                       // floats [64,128)
    float4 nz = ((const float4*)(noise + (size_t)row * LAT))[h];

    float4 z;
    z.x = mu.x + nz.x * __expf(0.5f * ls.x);
    z.y = mu.y + nz.y * __expf(0.5f * ls.y);
    z.z = mu.z + nz.z * __expf(0.5f * ls.z);
    z.w = mu.w + nz.w * __expf(0.5f * ls.w);

    float kl = -0.5f * (nz.x*nz.x + nz.y*nz.y + nz.z*nz.z + nz.w*nz.w
                      + ls.x + ls.y + ls.z + ls.w);

    // 32 biases per row, 2 regs per lane within the 16-lane group
    float bias_r[2];
    bias_r[0] = rp[BOFF + h];
    bias_r[1] = rp[BOFF + 16 + h];

    float logacc = 0.0f;

    #pragma unroll
    for (int k = 0; k < NSUPER; k++) {
        const uint32_t sb = wbase + (k & 1) * STAGE_BYTES;         // const after unroll
        const unsigned char* sp = pipe + warp * WARP_PIPE_BYTES + (k & 1) * STAGE_BYTES;

        // oldest committed group = super-stage k; wait, then pull 4 steps into regs
        CP_WAIT1();
        float4 ur[SUPER], wr[SUPER];
        #pragma unroll
        for (int j = 0; j < SUPER; j++) {
            ur[j] = *(const float4*)(sp + j * STEP_BYTES + lch);
            wr[j] = *(const float4*)(sp + j * STEP_BYTES + 512 + lch);
        }

        // refill this buffer for super-stage k+2 (1KB burst per stream); always commit
        if (k + 2 < NSUPER) {
            #pragma unroll
            for (int j = 0; j < SUPER; j++) {
                cp16(sb + j * STEP_BYTES + lch,       Ug + ((k + 2) * SUPER + j) * 256);
                cp16(sb + j * STEP_BYTES + 512 + lch, Wg + ((k + 2) * SUPER + j) * 256);
            }
        }
        CP_COMMIT();

        #pragma unroll
        for (int j = 0; j < SUPER; j++) {
            const int s = k * SUPER + j;
            // bias broadcast off the critical chain
            float bb = __shfl_sync(0xffffffffu, bias_r[s >> 4], (lane & 16) | (s & 15));

            float hl = (wr[j].x*z.x + wr[j].y*z.y) + (wr[j].z*z.z + wr[j].w*z.w);
            float ul = (ur[j].x*wr[j].x + ur[j].y*wr[j].y) + (ur[j].z*wr[j].z + ur[j].w*wr[j].w);

            // 4-level butterfly within each 16-lane (per-row) group
            #pragma unroll
            for (int o = 8; o > 0; o >>= 1) {
                hl += __shfl_xor_sync(0xffffffffu, hl, o);
                ul += __shfl_xor_sync(0xffffffffu, ul, o);
            }

            // tanh via fast exp: t = 1 - 2/(e^{2x}+1); correct limits at +/-inf
            float e = __expf(2.0f * (hl + bb));
            float t = 1.0f - __fdividef(2.0f, e + 1.0f);
            float x = (1.0f - t * t) * ul + 1.0f;
            logacc -= __logf(fabsf(x));

            z.x += ur[j].x * t;  z.y += ur[j].y * t;
            z.z += ur[j].z * t;  z.w += ur[j].w * t;
        }
    }

    // coalesced float4 z write (16 lanes cover the row's 64 floats)
    ((float4*)(out + (size_t)row * LAT))[h] = z;

    // reduce kl within the 16-lane row group
    #pragma unroll
    for (int o = 8; o > 0; o >>= 1)
        kl += __shfl_xor_sync(0xffffffffu, kl, o);

    float rt = kl + logacc;                     // per-row term, uniform per 16-lane group
    rt += __shfl_xor_sync(0xffffffffu, rt, 16); // sum the warp's 2 rows

    if (lane == 0) sacc[warp] = rt;
    __syncthreads();
    if (threadIdx.x == 0) {
        float sum = 0.0f;
        #pragma unroll
        for (int i = 0; i < WARPS_PER_BLOCK; i++) sum += sacc[i];
        g_partials[blockIdx.x] = sum;
        __threadfence();
        unsigned int tk = atomicAdd(&g_count, 1u);
        is_last = (tk == NBLOCKS - 1);
    }
    __syncthreads();

    // last block reduces all partials over a FIXED tree -> deterministic
    if (is_last) {
        float v = 0.0f;
        #pragma unroll
        for (int i = threadIdx.x; i < NBLOCKS; i += NTHREADS)
            v += g_partials[i];
        #pragma unroll
        for (int o = 16; o > 0; o >>= 1)
            v += __shfl_xor_sync(0xffffffffu, v, o);
        if (lane == 0) sacc[warp] = v;
        __syncthreads();
        if (threadIdx.x == 0) {
            float sum = 0.0f;
            #pragma unroll
            for (int i = 0; i < WARPS_PER_BLOCK; i++) sum += sacc[i];
            out[out_size - 1] = sum * (1.0f / (float)BATCH);
            g_count = 0;   // reset for next graph replay
        }
    }
}

extern "C" void kernel_launch(void* const* d_in, const int* in_sizes, int n_in,
                              void* d_out, int out_size)
{
    const float* in    = (const float*)d_in[0];
    const float* noise = (const float*)d_in[1];
    float*       out   = (float*)d_out;

    // 64KB dynamic smem per block (idempotent attribute sets, no allocation)
    cudaFuncSetAttribute(planar_flow_kernel,
                         cudaFuncAttributeMaxDynamicSharedMemorySize, SMEM_BYTES);
    cudaFuncSetAttribute(planar_flow_kernel,
                         cudaFuncAttributePreferredSharedMemoryCarveout, 100);

    planar_flow_kernel<<<NBLOCKS, NTHREADS, SMEM_BYTES>>>(in, noise, out, out_size);
}

// round 15
// speedup vs baseline: 1.1160x; 1.1160x over previous
#include <cuda_runtime.h>
#include <cstdint>

#define BATCH 16384
#define STEPS 32
#define LAT   64
#define IN_W  (STEPS * (2 * LAT + 1) + 2 * LAT)   // 4256 floats per row
#define WARPS_PER_BLOCK 4
#define NTHREADS (WARPS_PER_BLOCK * 32)           // 128
#define ROWS_PER_WARP 4
#define ROWS_PER_BLOCK (WARPS_PER_BLOCK * ROWS_PER_WARP)   // 16
#define NBLOCKS (BATCH / ROWS_PER_BLOCK)                   // 1024
#define BOFF ((2 + 2 * STEPS) * LAT)              // 4224: bias offset in row

#define STAGES 3
#define STAGE_BYTES 2048                          // per warp: u 1KB + w 1KB
#define WARP_PIPE_BYTES (STAGES * STAGE_BYTES)    // 6 KB per warp
// block smem: 4 * 6KB = 24KB -> 8 blocks/SM (192KB), single wave for grid=1024

// scratch for deterministic single-kernel loss reduction (no allocations allowed)
__device__ float g_partials[NBLOCKS];
__device__ unsigned int g_count = 0;   // ticket counter; last block resets to 0

__device__ __forceinline__ void cp16(uint32_t dst_smem, const void* src) {
    asm volatile("cp.async.cg.shared.global [%0], [%1], 16;\n"
                 :: "r"(dst_smem), "l"(src) : "memory");
}
#define CP_COMMIT() asm volatile("cp.async.commit_group;\n" ::: "memory")
#define CP_WAIT2()  asm volatile("cp.async.wait_group 2;\n" ::: "memory")

__global__ void __launch_bounds__(NTHREADS, 8)
planar_flow_kernel(const float* __restrict__ in,
                   const float* __restrict__ noise,
                   float* __restrict__ out, int out_size)
{
    __shared__ __align__(16) unsigned char pipe[WARPS_PER_BLOCK * WARP_PIPE_BYTES]; // 24 KB
    __shared__ float sacc[WARPS_PER_BLOCK];
    __shared__ bool  is_last;

    const int warp = threadIdx.x >> 5;
    const int lane = threadIdx.x & 31;
    const int h    = lane & 7;                     // position within my row's 8-lane group
    const int row  = blockIdx.x * ROWS_PER_BLOCK + warp * ROWS_PER_WARP + (lane >> 3);

    const float* rp = in + (size_t)row * IN_W;     // 17024 B/row: 16B aligned

    // global u/w byte pointers for THIS lane's 16B chunks (A at +h*16, B at +128+h*16)
    const char* Ug = (const char*)(rp + 2 * LAT)           + h * 16;
    const char* Wg = (const char*)(rp + (2 + STEPS) * LAT) + h * 16;

    // smem slot addresses for this lane (it reads back exactly what it writes)
    const uint32_t wbase = (uint32_t)__cvta_generic_to_shared(pipe) + warp * WARP_PIPE_BYTES;
    const uint32_t loff  = (lane >> 3) * 256 + h * 16;  // within the 1KB u (or w) block

    // ---- prologue: prime 3 pipeline stages (memory busy immediately) ----
    #pragma unroll
    for (int st = 0; st < STAGES; st++) {
        uint32_t sb = wbase + st * STAGE_BYTES;
        cp16(sb + loff,               Ug + st * 256);
        cp16(sb + loff + 128,         Ug + st * 256 + 128);
        cp16(sb + 1024 + loff,        Wg + st * 256);
        cp16(sb + 1024 + loff + 128,  Wg + st * 256 + 128);
        CP_COMMIT();
    }

    // --- z0 = mu + noise * exp(0.5*logsigma2), 8 elements per lane ---
    const float4* rp4 = (const float4*)rp;
    float4 muA = rp4[h],      muB = rp4[8 + h];        // floats [0,64)
    float4 lsA = rp4[16 + h], lsB = rp4[24 + h];       // floats [64,128)
    const float4* np4 = (const float4*)(noise + (size_t)row * LAT);
    float4 nzA = np4[h],      nzB = np4[8 + h];

    float4 zA, zB;
    zA.x = muA.x + nzA.x * __expf(0.5f * lsA.x);
    zA.y = muA.y + nzA.y * __expf(0.5f * lsA.y);
    zA.z = muA.z + nzA.z * __expf(0.5f * lsA.z);
    zA.w = muA.w + nzA.w * __expf(0.5f * lsA.w);
    zB.x = muB.x + nzB.x * __expf(0.5f * lsB.x);
    zB.y = muB.y + nzB.y * __expf(0.5f * lsB.y);
    zB.z = muB.z + nzB.z * __expf(0.5f * lsB.z);
    zB.w = muB.w + nzB.w * __expf(0.5f * lsB.w);

    float kl = -0.5f * (nzA.x*nzA.x + nzA.y*nzA.y + nzA.z*nzA.z + nzA.w*nzA.w
                      + nzB.x*nzB.x + nzB.y*nzB.y + nzB.z*nzB.z + nzB.w*nzB.w
                      + lsA.x + lsA.y + lsA.z + lsA.w
                      + lsB.x + lsB.y + lsB.z + lsB.w);

    // 32 biases per row, 4 regs per lane within the 8-lane group
    float bias_r[4];
    #pragma unroll
    for (int j = 0; j < 4; j++) bias_r[j] = rp[BOFF + j * 8 + h];

    float logacc = 0.0f;

    #pragma unroll
    for (int s = 0; s < STEPS; s++) {
        const int slot = s % STAGES;                       // literal after full unroll
        const uint32_t sb = wbase + slot * STAGE_BYTES;
        const unsigned char* sp = pipe + warp * WARP_PIPE_BYTES + slot * STAGE_BYTES;

        // oldest committed group = this stage; wait, then read our own 16B chunks
        CP_WAIT2();
        float4 ua = *(const float4*)(sp + loff);
        float4 ub = *(const float4*)(sp + loff + 128);
        float4 wa = *(const float4*)(sp + 1024 + loff);
        float4 wb = *(const float4*)(sp + 1024 + loff + 128);

        // refill this slot for step s+STAGES; always commit (keeps group accounting)
        if (s + STAGES < STEPS) {
            cp16(sb + loff,              Ug + (s + STAGES) * 256);
            cp16(sb + loff + 128,        Ug + (s + STAGES) * 256 + 128);
            cp16(sb + 1024 + loff,       Wg + (s + STAGES) * 256);
            cp16(sb + 1024 + loff + 128, Wg + (s + STAGES) * 256 + 128);
        }
        CP_COMMIT();

        // bias broadcast off the critical chain
        float bb = __shfl_sync(0xffffffffu, bias_r[s >> 3], (lane & 24) | (s & 7));

        // balanced product trees for partials
        float hl = ((wa.x*zA.x + wa.y*zA.y) + (wa.z*zA.z + wa.w*zA.w))
                 + ((wb.x*zB.x + wb.y*zB.y) + (wb.z*zB.z + wb.w*zB.w));
        float ul = ((ua.x*wa.x + ua.y*wa.y) + (ua.z*wa.z + ua.w*wa.w))
                 + ((ub.x*wb.x + ub.y*wb.y) + (ub.z*wb.z + ub.w*wb.w));

        // 3-level butterfly within each 8-lane (per-row) group
        #pragma unroll
        for (int o = 4; o > 0; o >>= 1) {
            hl += __shfl_xor_sync(0xffffffffu, hl, o);
            ul += __shfl_xor_sync(0xffffffffu, ul, o);
        }

        // tanh via fast exp: t = 1 - 2/(e^{2x}+1); correct limits at +/-inf
        float e = __expf(2.0f * (hl + bb));
        float t = 1.0f - __fdividef(2.0f, e + 1.0f);
        float x = (1.0f - t * t) * ul + 1.0f;
        logacc -= __logf(fabsf(x));

        zA.x += ua.x * t;  zA.y += ua.y * t;  zA.z += ua.z * t;  zA.w += ua.w * t;
        zB.x += ub.x * t;  zB.y += ub.y * t;  zB.z += ub.z * t;  zB.w += ub.w * t;
    }

    // coalesced float4 z writes (contiguous 128B per row per instruction)
    float4* op4 = (float4*)(out + (size_t)row * LAT);
    op4[h]     = zA;
    op4[8 + h] = zB;

    // reduce kl within the 8-lane row group
    #pragma unroll
    for (int o = 4; o > 0; o >>= 1)
        kl += __shfl_xor_sync(0xffffffffu, kl, o);

    float rt = kl + logacc;                     // per-row term, uniform per 8-lane group
    rt += __shfl_xor_sync(0xffffffffu, rt, 8);  // sum the warp's 4 rows
    rt += __shfl_xor_sync(0xffffffffu, rt, 16);

    if (lane == 0) sacc[warp] = rt;
    __syncthreads();
    if (threadIdx.x == 0) {
        float sum = 0.0f;
        #pragma unroll
        for (int i = 0; i < WARPS_PER_BLOCK; i++) sum += sacc[i];
        g_partials[blockIdx.x] = sum;
        __threadfence();
        unsigned int tk = atomicAdd(&g_count, 1u);
        is_last = (tk == NBLOCKS - 1);
    }
    __syncthreads();

    // last block reduces all partials over a FIXED tree -> deterministic
    if (is_last) {
        float v = 0.0f;
        #pragma unroll
        for (int i = threadIdx.x; i < NBLOCKS; i += NTHREADS)
            v += g_partials[i];
        #pragma unroll
        for (int o = 16; o > 0; o >>= 1)
            v += __shfl_xor_sync(0xffffffffu, v, o);
        if (lane == 0) sacc[warp] = v;
        __syncthreads();
        if (threadIdx.x == 0) {
            float sum = 0.0f;
            #pragma unroll
            for (int i = 0; i < WARPS_PER_BLOCK; i++) sum += sacc[i];
            out[out_size - 1] = sum * (1.0f / (float)BATCH);
            g_count = 0;   // reset for next graph replay
        }
    }
}

extern "C" void kernel_launch(void* const* d_in, const int* in_sizes, int n_in,
                              void* d_out, int out_size)
{
    const float* in    = (const float*)d_in[0];
    const float* noise = (const float*)d_in[1];
    float*       out   = (float*)d_out;

    // maximize smem carveout so 8 blocks/SM fit (idempotent, no allocation)
    cudaFuncSetAttribute(planar_flow_kernel,
                         cudaFuncAttributePreferredSharedMemoryCarveout, 100);

    planar_flow_kernel<<<NBLOCKS, NTHREADS>>>(in, noise, out, out_size);
}